// round 7
// baseline (speedup 1.0000x reference)
#include <cuda_runtime.h>
#include <cuda_bf16.h>
#include <cuda_fp16.h>
#include <math.h>
#include <stdint.h>

// Problem constants (fixed by setup_inputs)
#define NN      50000
#define EE      800000
#define F_IN    128
#define WID     128
#define F_OUT   64
#define KK      128          // inner dim is 128 for every layer

#define SCAN_B  1024
#define SCAN_NB ((NN + SCAN_B - 1) / SCAN_B)   // 49

// ---------------- device scratch (no allocation allowed) ----------------
__device__ float g_h[NN * WID];               // hidden state ping buffer
__device__ float g_abc[NN * (3 * WID)];       // GEMM output: a | d  (2*WID used)
__device__ float g_Wcat0[F_IN * 3 * WID];     // packed weights: in layer
__device__ float g_Wcat1[WID * 3 * WID];      // packed weights: mid layer
__device__ float g_Wcat2[WID * 3 * F_OUT];    // packed weights: out layer
__device__ float g_bcat0[3 * WID];
__device__ float g_bcat1[3 * WID];
__device__ float g_bcat2[3 * F_OUT];
__device__ float g_s[NN];                     // per-node sum of incoming edge weights
__device__ int   g_deg[NN];
__device__ int   g_rowptr[NN + 1];
__device__ int   g_cursor[NN];
__device__ int   g_bsum[SCAN_NB];
__device__ int   g_boff[SCAN_NB];
__device__ int   g_src[EE];
__device__ float g_ew[EE];
__device__ int   g_is64;                      // edge_index dtype flag (1 = int64)

__device__ __forceinline__ int edge_idx(const void* ei, int idx) {
    if (g_is64) return (int)((const long long*)ei)[idx];
    return ((const int*)ei)[idx];
}

// ---------------- preprocessing ----------------
__global__ void zero_kernel(const int* __restrict__ ei_raw) {
    int i = blockIdx.x * blockDim.x + threadIdx.x;
    if (i < NN) { g_deg[i] = 0; g_s[i] = 0.f; }
    if (blockIdx.x == 0 && threadIdx.x == 0) {
        int is64 = 1;
        for (int t = 0; t < 64; t++)
            if (ei_raw[2 * t + 1] != 0) { is64 = 0; break; }
        g_is64 = is64;
    }
}

__global__ void hist_kernel(const void* __restrict__ ei,
                            const float* __restrict__ ea) {
    int e = blockIdx.x * blockDim.x + threadIdx.x;
    if (e < EE) {
        int dst = edge_idx(ei, EE + e);
        if ((unsigned)dst >= NN) return;
        atomicAdd(&g_deg[dst], 1);
        atomicAdd(&g_s[dst], ea[e]);
    }
}

__global__ __launch_bounds__(SCAN_B) void scan1_kernel() {
    __shared__ int wsum[32];
    int i = blockIdx.x * SCAN_B + threadIdx.x;
    int lane = threadIdx.x & 31;
    int wid  = threadIdx.x >> 5;
    int v = (i < NN) ? g_deg[i] : 0;
    int incl = v;
    #pragma unroll
    for (int off = 1; off < 32; off <<= 1) {
        int t = __shfl_up_sync(0xffffffffu, incl, off);
        if (lane >= off) incl += t;
    }
    if (lane == 31) wsum[wid] = incl;
    __syncthreads();
    if (wid == 0) {
        int s = wsum[lane];
        #pragma unroll
        for (int off = 1; off < 32; off <<= 1) {
            int t = __shfl_up_sync(0xffffffffu, s, off);
            if (lane >= off) s += t;
        }
        wsum[lane] = s;
    }
    __syncthreads();
    if (wid > 0) incl += wsum[wid - 1];
    if (i < NN) g_rowptr[i + 1] = incl;
    if (threadIdx.x == SCAN_B - 1) g_bsum[blockIdx.x] = incl;
}

__global__ void scan2_kernel() {
    if (threadIdx.x == 0) {
        int run = 0;
        for (int b = 0; b < SCAN_NB; b++) { g_boff[b] = run; run += g_bsum[b]; }
    }
}

__global__ __launch_bounds__(SCAN_B) void scan3_kernel() {
    int i = blockIdx.x * SCAN_B + threadIdx.x;
    if (i < NN) {
        int rp = g_rowptr[i + 1] + g_boff[blockIdx.x];
        g_rowptr[i + 1] = rp;
        g_cursor[i] = rp - g_deg[i];
    }
    if (i == 0) g_rowptr[0] = 0;
}

__global__ void scatter_kernel(const void* __restrict__ ei,
                               const float* __restrict__ ea) {
    int e = blockIdx.x * blockDim.x + threadIdx.x;
    if (e < EE) {
        int src = edge_idx(ei, e);
        int dst = edge_idx(ei, EE + e);
        if ((unsigned)src >= NN || (unsigned)dst >= NN) return;
        int pos = atomicAdd(&g_cursor[dst], 1);
        g_src[pos] = src;
        g_ew[pos]  = ea[e];
    }
}

// ---------------- weight packing: Wcat = [W1 | interleave(W2, W3)] ----------------
__global__ void pack_w_kernel(const float* __restrict__ W1, const float* __restrict__ b1,
                              const float* __restrict__ W2,
                              const float* __restrict__ W3, const float* __restrict__ b3,
                              int K, int C, float* __restrict__ Wcat, float* __restrict__ bcat) {
    int i = blockIdx.x * blockDim.x + threadIdx.x;
    int total = K * C;
    if (i < total) {
        int k = i / C, c = i % C;
        Wcat[k * 3 * C + c]             = W1[i];
        Wcat[k * 3 * C + C + 2 * c]     = W2[i];
        Wcat[k * 3 * C + C + 2 * c + 1] = W3[i];
    }
    if (i < C) {
        bcat[i]             = b1[i];
        bcat[C + 2 * i]     = 0.f;
        bcat[C + 2 * i + 1] = b3[i];
    }
}

// ========== tensor-core GEMM (3xFP16 Markidis split, m16n8k16) + fused LEConv epilogue ==========
#define AS_S 36     // As padded stride (words)
#define BS_S 132    // Bs padded stride (words)
#define TG_SMEM ((2 * 128 * AS_S + 128 * BS_S) * 4)   // 104448 bytes

// split fp32 pair (k-adjacent) into packed f16x2 hi and lo: p = hi + lo (+ ~2^-22 residual)
__device__ __forceinline__ void split_f16(float2 p, uint32_t& hi, uint32_t& lo) {
    __half2 h = __float22half2_rn(p);         // low half = p.x (k0), high half = p.y (k1)
    hi = *reinterpret_cast<uint32_t*>(&h);
    float2 hf = __half22float2(h);
    __half2 l = __float22half2_rn(make_float2(p.x - hf.x, p.y - hf.y));
    lo = *reinterpret_cast<uint32_t*>(&l);
}

#define MMA_F16(d, a0, a1, a2, a3, b0, b1)                                              \
    asm volatile("mma.sync.aligned.m16n8k16.row.col.f32.f16.f16.f32 "                    \
                 "{%0,%1,%2,%3},{%4,%5,%6,%7},{%8,%9},{%0,%1,%2,%3};"                    \
                 : "+f"(d[0]), "+f"(d[1]), "+f"(d[2]), "+f"(d[3])                        \
                 : "r"(a0), "r"(a1), "r"(a2), "r"(a3), "r"(b0), "r"(b1))

__global__ __launch_bounds__(256, 1) void tgemm_kernel(const float* __restrict__ A,
                                                       const float* __restrict__ W,
                                                       const float* __restrict__ bias,
                                                       const float* __restrict__ svec,
                                                       int M, int AC,
                                                       float* __restrict__ out) {
    extern __shared__ float sm[];
    float* As = sm;                       // [2][128][AS_S]
    float* Bs = sm + 2 * 128 * AS_S;      // [128 n][BS_S] full-K transposed W tile

    const int Ncol = 3 * AC;
    const int OS   = 2 * AC;
    const int tid = threadIdx.x;
    const int lane = tid & 31;
    const int g  = lane >> 2;     // 0..7
    const int tq = lane & 3;      // 0..3
    const int warp = tid >> 5;
    const int wm = warp & 1;      // m half
    const int wn = warp >> 1;     // n quarter
    const int row0 = blockIdx.x * 128;
    const int col0 = blockIdx.y * 128;

    const uint32_t as_base = (uint32_t)__cvta_generic_to_shared(As);

    auto load_a = [&](int s, int buf) {
        int k0 = s * 32;
        #pragma unroll
        for (int p = 0; p < 4; p++) {
            int f = tid + p * 256;
            int row = f >> 3, c4 = f & 7;
            bool valid = (row0 + row) < M;
            size_t grow = valid ? (size_t)(row0 + row) : 0;
            const float* gp = A + grow * KK + k0 + c4 * 4;
            uint32_t sp = as_base + (uint32_t)((buf * 128 * AS_S + row * AS_S + c4 * 4) * 4);
            int bytes = valid ? 16 : 0;
            asm volatile("cp.async.ca.shared.global [%0], [%1], 16, %2;"
                         :: "r"(sp), "l"(gp), "r"(bytes));
        }
        asm volatile("cp.async.commit_group;");
    };

    // ---- prologue ----
    load_a(0, 0);
    load_a(1, 1);
    {
        int n = tid & 127;
        int kqb = tid >> 7;
        bool nval = (col0 + n) < Ncol;
        #pragma unroll
        for (int i2 = 0; i2 < 16; i2++) {
            int kr = (kqb + i2 * 2) * 4;
            float4 v = make_float4(0.f, 0.f, 0.f, 0.f);
            if (nval) {
                v.x = W[(size_t)(kr + 0) * Ncol + col0 + n];
                v.y = W[(size_t)(kr + 1) * Ncol + col0 + n];
                v.z = W[(size_t)(kr + 2) * Ncol + col0 + n];
                v.w = W[(size_t)(kr + 3) * Ncol + col0 + n];
            }
            *reinterpret_cast<float4*>(&Bs[n * BS_S + kr]) = v;
        }
    }
    asm volatile("cp.async.wait_group 1;");
    __syncthreads();

    float acc[4][4][4];
    #pragma unroll
    for (int i = 0; i < 4; i++)
        #pragma unroll
        for (int j = 0; j < 4; j++)
            #pragma unroll
            for (int q = 0; q < 4; q++) acc[i][j][q] = 0.f;

    // ---- main loop: 4 stages of BK=32, each = 2 k16 steps ----
    #pragma unroll
    for (int t = 0; t < 4; t++) {
        const float* as = As + (t & 1) * (128 * AS_S);

        #pragma unroll
        for (int kk = 0; kk < 2; kk++) {
            const int ksl = kk * 16;           // k offset within stage
            const int ksg = t * 32 + ksl;      // global k offset (for Bs)

            // A fragments (m16n8k16): pairs along k
            uint32_t ahi[4][4], alo[4][4];
            #pragma unroll
            for (int i = 0; i < 4; i++) {
                int r0 = wm * 64 + i * 16 + g;
                float2 p0 = *reinterpret_cast<const float2*>(&as[r0 * AS_S + ksl + 2 * tq]);
                float2 p1 = *reinterpret_cast<const float2*>(&as[(r0 + 8) * AS_S + ksl + 2 * tq]);
                float2 p2 = *reinterpret_cast<const float2*>(&as[r0 * AS_S + ksl + 2 * tq + 8]);
                float2 p3 = *reinterpret_cast<const float2*>(&as[(r0 + 8) * AS_S + ksl + 2 * tq + 8]);
                split_f16(p0, ahi[i][0], alo[i][0]);
                split_f16(p1, ahi[i][1], alo[i][1]);
                split_f16(p2, ahi[i][2], alo[i][2]);
                split_f16(p3, ahi[i][3], alo[i][3]);
            }
            // B fragments
            uint32_t bhi[4][2], blo[4][2];
            #pragma unroll
            for (int j = 0; j < 4; j++) {
                int nn = wn * 32 + j * 8 + g;
                float2 q0 = *reinterpret_cast<const float2*>(&Bs[nn * BS_S + ksg + 2 * tq]);
                float2 q1 = *reinterpret_cast<const float2*>(&Bs[nn * BS_S + ksg + 2 * tq + 8]);
                split_f16(q0, bhi[j][0], blo[j][0]);
                split_f16(q1, bhi[j][1], blo[j][1]);
            }
            #pragma unroll
            for (int i = 0; i < 4; i++)
                #pragma unroll
                for (int j = 0; j < 4; j++) {
                    MMA_F16(acc[i][j], ahi[i][0], ahi[i][1], ahi[i][2], ahi[i][3], bhi[j][0], bhi[j][1]);
                    MMA_F16(acc[i][j], ahi[i][0], ahi[i][1], ahi[i][2], ahi[i][3], blo[j][0], blo[j][1]);
                    MMA_F16(acc[i][j], alo[i][0], alo[i][1], alo[i][2], alo[i][3], bhi[j][0], bhi[j][1]);
                }
        }

        if (t < 3) {
            __syncthreads();                       // done reading buffer (t&1)
            if (t + 2 < 4) load_a(t + 2, t & 1);   // refill freed buffer
            asm volatile("cp.async.wait_group %0;" :: "n"(1));
            if (t == 2) asm volatile("cp.async.wait_group 0;");
            __syncthreads();
        }
    }

    // ---- fused epilogue ----
    #pragma unroll
    for (int i = 0; i < 4; i++) {
        int gm0 = row0 + wm * 64 + i * 16 + g;
        int gm1 = gm0 + 8;
        float s0 = (gm0 < M) ? svec[gm0] : 0.f;
        float s1 = (gm1 < M) ? svec[gm1] : 0.f;
        #pragma unroll
        for (int j = 0; j < 4; j++) {
            int gn = col0 + wn * 32 + j * 8 + 2 * tq;
            if (gn >= Ncol) continue;
            if (gn < AC) {
                float2 bb = *reinterpret_cast<const float2*>(bias + gn);
                if (gm0 < M) {
                    float2 v0 = make_float2(acc[i][j][0] + bb.x, acc[i][j][1] + bb.y);
                    *reinterpret_cast<float2*>(out + (size_t)gm0 * OS + gn) = v0;
                }
                if (gm1 < M) {
                    float2 v1 = make_float2(acc[i][j][2] + bb.x, acc[i][j][3] + bb.y);
                    *reinterpret_cast<float2*>(out + (size_t)gm1 * OS + gn) = v1;
                }
            } else {
                int u = (gn - AC) >> 1;
                float b3v = bias[gn + 1];
                if (gm0 < M)
                    out[(size_t)gm0 * OS + AC + u] = (acc[i][j][1] + b3v) - s0 * acc[i][j][0];
                if (gm1 < M)
                    out[(size_t)gm1 * OS + AC + u] = (acc[i][j][3] + b3v) - s1 * acc[i][j][2];
            }
        }
    }
}

// ---------------- SpMM + epilogue, F=128 (one warp per node, float4 per lane) ----------------
__global__ __launch_bounds__(256) void spmm128_kernel(const float* __restrict__ ad,
                                                      float* __restrict__ out,
                                                      int act) {
    const int F = 128;
    const int stride = 2 * F;
    int w = blockIdx.x * 8 + (threadIdx.x >> 5);
    if (w >= NN) return;
    int lane = threadIdx.x & 31;
    int fbase = lane * 4;

    float4 acc = make_float4(0.f, 0.f, 0.f, 0.f);
    int beg = g_rowptr[w], end = g_rowptr[w + 1];
    int e = beg;
    for (; e + 3 < end; e += 4) {
        int   s0 = g_src[e],   s1 = g_src[e+1], s2 = g_src[e+2], s3 = g_src[e+3];
        float w0 = g_ew[e],    w1 = g_ew[e+1],  w2 = g_ew[e+2],  w3 = g_ew[e+3];
        float4 a0 = *reinterpret_cast<const float4*>(ad + (size_t)s0 * stride + fbase);
        float4 a1 = *reinterpret_cast<const float4*>(ad + (size_t)s1 * stride + fbase);
        float4 a2 = *reinterpret_cast<const float4*>(ad + (size_t)s2 * stride + fbase);
        float4 a3 = *reinterpret_cast<const float4*>(ad + (size_t)s3 * stride + fbase);
        acc.x += w0 * a0.x + w1 * a1.x + w2 * a2.x + w3 * a3.x;
        acc.y += w0 * a0.y + w1 * a1.y + w2 * a2.y + w3 * a3.y;
        acc.z += w0 * a0.z + w1 * a1.z + w2 * a2.z + w3 * a3.z;
        acc.w += w0 * a0.w + w1 * a1.w + w2 * a2.w + w3 * a3.w;
    }
    for (; e < end; e++) {
        int   s0 = g_src[e];
        float w0 = g_ew[e];
        float4 a0 = *reinterpret_cast<const float4*>(ad + (size_t)s0 * stride + fbase);
        acc.x += w0 * a0.x; acc.y += w0 * a0.y; acc.z += w0 * a0.z; acc.w += w0 * a0.w;
    }
    float4 dv = *reinterpret_cast<const float4*>(ad + (size_t)w * stride + F + fbase);
    float v[4];
    v[0] = acc.x + dv.x;
    v[1] = acc.y + dv.y;
    v[2] = acc.z + dv.z;
    v[3] = acc.w + dv.w;
    #pragma unroll
    for (int i = 0; i < 4; i++) {
        float t = v[i] > 0.f ? v[i] : 0.1f * v[i];
        if (act == 1) t = 1.f / (1.f + expf(-t));
        v[i] = t;
    }
    *reinterpret_cast<float4*>(out + (size_t)w * F + fbase) =
        make_float4(v[0], v[1], v[2], v[3]);
}

// ---------------- SpMM + epilogue, F=64 (one warp per node, float2 per lane) ----------------
__global__ __launch_bounds__(256) void spmm64_kernel(const float* __restrict__ ad,
                                                     float* __restrict__ out,
                                                     int act) {
    const int F = 64;
    const int stride = 2 * F;
    int w = blockIdx.x * 8 + (threadIdx.x >> 5);
    if (w >= NN) return;
    int lane = threadIdx.x & 31;
    int fbase = lane * 2;

    float2 acc = make_float2(0.f, 0.f);
    int beg = g_rowptr[w], end = g_rowptr[w + 1];
    int e = beg;
    for (; e + 3 < end; e += 4) {
        int   s0 = g_src[e],   s1 = g_src[e+1], s2 = g_src[e+2], s3 = g_src[e+3];
        float w0 = g_ew[e],    w1 = g_ew[e+1],  w2 = g_ew[e+2],  w3 = g_ew[e+3];
        float2 a0 = *reinterpret_cast<const float2*>(ad + (size_t)s0 * stride + fbase);
        float2 a1 = *reinterpret_cast<const float2*>(ad + (size_t)s1 * stride + fbase);
        float2 a2 = *reinterpret_cast<const float2*>(ad + (size_t)s2 * stride + fbase);
        float2 a3 = *reinterpret_cast<const float2*>(ad + (size_t)s3 * stride + fbase);
        acc.x += w0 * a0.x + w1 * a1.x + w2 * a2.x + w3 * a3.x;
        acc.y += w0 * a0.y + w1 * a1.y + w2 * a2.y + w3 * a3.y;
    }
    for (; e < end; e++) {
        int   s0 = g_src[e];
        float w0 = g_ew[e];
        float2 a0 = *reinterpret_cast<const float2*>(ad + (size_t)s0 * stride + fbase);
        acc.x += w0 * a0.x; acc.y += w0 * a0.y;
    }
    float2 dv = *reinterpret_cast<const float2*>(ad + (size_t)w * stride + F + fbase);
    float v[2];
    v[0] = acc.x + dv.x;
    v[1] = acc.y + dv.y;
    #pragma unroll
    for (int i = 0; i < 2; i++) {
        float t = v[i] > 0.f ? v[i] : 0.1f * v[i];
        if (act == 1) t = 1.f / (1.f + expf(-t));
        v[i] = t;
    }
    *reinterpret_cast<float2*>(out + (size_t)w * F + fbase) = make_float2(v[0], v[1]);
}

// ---------------- host launch ----------------
extern "C" void kernel_launch(void* const* d_in, const int* in_sizes, int n_in,
                              void* d_out, int out_size) {
    const float* x  = (const float*)d_in[0];
    const void*  ei = d_in[1];
    const float* ea = (const float*)d_in[2];
    const float* W1_in  = (const float*)d_in[4];
    const float* b1_in  = (const float*)d_in[5];
    const float* W2_in  = (const float*)d_in[6];
    const float* W3_in  = (const float*)d_in[7];
    const float* b3_in  = (const float*)d_in[8];
    const float* W1_mid = (const float*)d_in[9];
    const float* b1_mid = (const float*)d_in[10];
    const float* W2_mid = (const float*)d_in[11];
    const float* W3_mid = (const float*)d_in[12];
    const float* b3_mid = (const float*)d_in[13];
    const float* W1_out = (const float*)d_in[14];
    const float* b1_out = (const float*)d_in[15];
    const float* W2_out = (const float*)d_in[16];
    const float* W3_out = (const float*)d_in[17];
    const float* b3_out = (const float*)d_in[18];

    float* out = (float*)d_out;

    float *d_h, *d_abc, *d_W0, *d_W1, *d_W2, *d_b0, *d_b1, *d_b2, *d_s;
    cudaGetSymbolAddress((void**)&d_h,   g_h);
    cudaGetSymbolAddress((void**)&d_abc, g_abc);
    cudaGetSymbolAddress((void**)&d_W0,  g_Wcat0);
    cudaGetSymbolAddress((void**)&d_W1,  g_Wcat1);
    cudaGetSymbolAddress((void**)&d_W2,  g_Wcat2);
    cudaGetSymbolAddress((void**)&d_b0,  g_bcat0);
    cudaGetSymbolAddress((void**)&d_b1,  g_bcat1);
    cudaGetSymbolAddress((void**)&d_b2,  g_bcat2);
    cudaGetSymbolAddress((void**)&d_s,   g_s);

    cudaFuncSetAttribute(tgemm_kernel, cudaFuncAttributeMaxDynamicSharedMemorySize, TG_SMEM);

    // --- pack all weights up front ---
    pack_w_kernel<<<(F_IN * WID + 255) / 256, 256>>>(W1_in,  b1_in,  W2_in,  W3_in,  b3_in,  F_IN, WID,   d_W0, d_b0);
    pack_w_kernel<<<(WID * WID + 255) / 256, 256>>>(W1_mid, b1_mid, W2_mid, W3_mid, b3_mid, WID,  WID,   d_W1, d_b1);
    pack_w_kernel<<<(WID * F_OUT + 255) / 256, 256>>>(W1_out, b1_out, W2_out, W3_out, b3_out, WID, F_OUT, d_W2, d_b2);

    // --- preprocessing: zero+detect, s[i], CSR ---
    zero_kernel<<<(NN + 255) / 256, 256>>>((const int*)ei);
    hist_kernel<<<(EE + 255) / 256, 256>>>(ei, ea);
    scan1_kernel<<<SCAN_NB, SCAN_B>>>();
    scan2_kernel<<<1, 32>>>();
    scan3_kernel<<<SCAN_NB, SCAN_B>>>();
    scatter_kernel<<<(EE + 255) / 256, 256>>>(ei, ea);

    const int spmm_blocks = (NN + 7) / 8;
    const int grid_m = (NN + 127) / 128;

    // --- layer 0 (in): x -> g_h ---
    {
        dim3 grid(grid_m, (3 * WID + 127) / 128);
        tgemm_kernel<<<grid, 256, TG_SMEM>>>(x, d_W0, d_b0, d_s, NN, WID, d_abc);
        spmm128_kernel<<<spmm_blocks, 256>>>(d_abc, d_h, 0);
    }

    // --- layers 1,2 (mid): g_h -> g_h ---
    for (int l = 0; l < 2; l++) {
        dim3 grid(grid_m, (3 * WID + 127) / 128);
        tgemm_kernel<<<grid, 256, TG_SMEM>>>(d_h, d_W1, d_b1, d_s, NN, WID, d_abc);
        spmm128_kernel<<<spmm_blocks, 256>>>(d_abc, d_h, 0);
    }

    // --- layer 3 (out): g_h -> d_out (lrelu then sigmoid) ---
    {
        dim3 grid(grid_m, (3 * F_OUT + 127) / 128);
        tgemm_kernel<<<grid, 256, TG_SMEM>>>(d_h, d_W2, d_b2, d_s, NN, F_OUT, d_abc);
        spmm64_kernel<<<spmm_blocks, 256>>>(d_abc, out, 1);
    }
}

// round 8
// speedup vs baseline: 1.3187x; 1.3187x over previous
#include <cuda_runtime.h>
#include <cuda_bf16.h>
#include <cuda_fp16.h>
#include <math.h>
#include <stdint.h>

// Problem constants (fixed by setup_inputs)
#define NN      50000
#define EE      800000
#define F_IN    128
#define WID     128
#define F_OUT   64
#define KK      128          // inner dim is 128 for every layer

#define SCAN_B  1024
#define SCAN_NB ((NN + SCAN_B - 1) / SCAN_B)   // 49

// ---------------- device scratch (no allocation allowed) ----------------
__device__ __align__(16) __half g_Ahi[NN * KK];     // split activations (input to GEMM)
__device__ __align__(16) __half g_Alo[NN * KK];
__device__ float g_abc[NN * (3 * WID)];             // GEMM output: a | d (2*WID used)
__device__ __align__(16) __half g_Wthi0[3 * WID * KK];  // pre-split transposed weights [Ncol][K]
__device__ __align__(16) __half g_Wtlo0[3 * WID * KK];
__device__ __align__(16) __half g_Wthi1[3 * WID * KK];
__device__ __align__(16) __half g_Wtlo1[3 * WID * KK];
__device__ __align__(16) __half g_Wthi2[3 * F_OUT * KK];
__device__ __align__(16) __half g_Wtlo2[3 * F_OUT * KK];
__device__ float g_bcat0[3 * WID];
__device__ float g_bcat1[3 * WID];
__device__ float g_bcat2[3 * F_OUT];
__device__ float g_s[NN];
__device__ int   g_deg[NN];
__device__ int   g_rowptr[NN + 1];
__device__ int   g_cursor[NN];
__device__ int   g_bsum[SCAN_NB];
__device__ int   g_boff[SCAN_NB];
__device__ int   g_src[EE];
__device__ float g_ew[EE];
__device__ int   g_is64;

__device__ __forceinline__ int edge_idx(const void* ei, int idx) {
    if (g_is64) return (int)((const long long*)ei)[idx];
    return ((const int*)ei)[idx];
}

__device__ __forceinline__ void split1(float v, __half& hi, __half& lo) {
    hi = __float2half_rn(v);
    lo = __float2half_rn(v - __half2float(hi));
}

// ---------------- preprocessing ----------------
__global__ void zero_kernel(const int* __restrict__ ei_raw) {
    int i = blockIdx.x * blockDim.x + threadIdx.x;
    if (i < NN) { g_deg[i] = 0; g_s[i] = 0.f; }
    if (blockIdx.x == 0 && threadIdx.x == 0) {
        int is64 = 1;
        for (int t = 0; t < 64; t++)
            if (ei_raw[2 * t + 1] != 0) { is64 = 0; break; }
        g_is64 = is64;
    }
}

// split x into fp16 hi/lo (one shot, layer-0 input)
__global__ void convert_x_kernel(const float4* __restrict__ x4, int n4) {
    int i = blockIdx.x * blockDim.x + threadIdx.x;
    if (i >= n4) return;
    float4 v = x4[i];
    __half2 h01 = __float22half2_rn(make_float2(v.x, v.y));
    __half2 h23 = __float22half2_rn(make_float2(v.z, v.w));
    float2 f01 = __half22float2(h01);
    float2 f23 = __half22float2(h23);
    __half2 l01 = __float22half2_rn(make_float2(v.x - f01.x, v.y - f01.y));
    __half2 l23 = __float22half2_rn(make_float2(v.z - f23.x, v.w - f23.y));
    uint2 uh = make_uint2(*reinterpret_cast<uint32_t*>(&h01), *reinterpret_cast<uint32_t*>(&h23));
    uint2 ul = make_uint2(*reinterpret_cast<uint32_t*>(&l01), *reinterpret_cast<uint32_t*>(&l23));
    *reinterpret_cast<uint2*>(g_Ahi + (size_t)i * 4) = uh;
    *reinterpret_cast<uint2*>(g_Alo + (size_t)i * 4) = ul;
}

__global__ void hist_kernel(const void* __restrict__ ei,
                            const float* __restrict__ ea) {
    int e = blockIdx.x * blockDim.x + threadIdx.x;
    if (e < EE) {
        int dst = edge_idx(ei, EE + e);
        if ((unsigned)dst >= NN) return;
        atomicAdd(&g_deg[dst], 1);
        atomicAdd(&g_s[dst], ea[e]);
    }
}

__global__ __launch_bounds__(SCAN_B) void scan1_kernel() {
    __shared__ int wsum[32];
    int i = blockIdx.x * SCAN_B + threadIdx.x;
    int lane = threadIdx.x & 31;
    int wid  = threadIdx.x >> 5;
    int v = (i < NN) ? g_deg[i] : 0;
    int incl = v;
    #pragma unroll
    for (int off = 1; off < 32; off <<= 1) {
        int t = __shfl_up_sync(0xffffffffu, incl, off);
        if (lane >= off) incl += t;
    }
    if (lane == 31) wsum[wid] = incl;
    __syncthreads();
    if (wid == 0) {
        int s = wsum[lane];
        #pragma unroll
        for (int off = 1; off < 32; off <<= 1) {
            int t = __shfl_up_sync(0xffffffffu, s, off);
            if (lane >= off) s += t;
        }
        wsum[lane] = s;
    }
    __syncthreads();
    if (wid > 0) incl += wsum[wid - 1];
    if (i < NN) g_rowptr[i + 1] = incl;
    if (threadIdx.x == SCAN_B - 1) g_bsum[blockIdx.x] = incl;
}

__global__ void scan2_kernel() {
    if (threadIdx.x == 0) {
        int run = 0;
        for (int b = 0; b < SCAN_NB; b++) { g_boff[b] = run; run += g_bsum[b]; }
    }
}

__global__ __launch_bounds__(SCAN_B) void scan3_kernel() {
    int i = blockIdx.x * SCAN_B + threadIdx.x;
    if (i < NN) {
        int rp = g_rowptr[i + 1] + g_boff[blockIdx.x];
        g_rowptr[i + 1] = rp;
        g_cursor[i] = rp - g_deg[i];
    }
    if (i == 0) g_rowptr[0] = 0;
}

__global__ void scatter_kernel(const void* __restrict__ ei,
                               const float* __restrict__ ea) {
    int e = blockIdx.x * blockDim.x + threadIdx.x;
    if (e < EE) {
        int src = edge_idx(ei, e);
        int dst = edge_idx(ei, EE + e);
        if ((unsigned)src >= NN || (unsigned)dst >= NN) return;
        int pos = atomicAdd(&g_cursor[dst], 1);
        g_src[pos] = src;
        g_ew[pos]  = ea[e];
    }
}

// ------- weight packing: transposed + pre-split. Wt[col][k], col map: [W1 | interleave(W2,W3)] -------
__global__ void pack_w_kernel(const float* __restrict__ W1, const float* __restrict__ b1,
                              const float* __restrict__ W2,
                              const float* __restrict__ W3, const float* __restrict__ b3,
                              int K, int C,
                              __half* __restrict__ Wthi, __half* __restrict__ Wtlo,
                              float* __restrict__ bcat) {
    int i = blockIdx.x * blockDim.x + threadIdx.x;
    int total = K * C;
    if (i < total) {
        int k = i / C, c = i % C;
        __half h, l;
        split1(W1[i], h, l);
        Wthi[(size_t)c * KK + k] = h;               Wtlo[(size_t)c * KK + k] = l;
        split1(W2[i], h, l);
        Wthi[(size_t)(C + 2 * c) * KK + k] = h;     Wtlo[(size_t)(C + 2 * c) * KK + k] = l;
        split1(W3[i], h, l);
        Wthi[(size_t)(C + 2 * c + 1) * KK + k] = h; Wtlo[(size_t)(C + 2 * c + 1) * KK + k] = l;
    }
    if (i < C) {
        bcat[i]             = b1[i];
        bcat[C + 2 * i]     = 0.f;
        bcat[C + 2 * i + 1] = b3[i];
    }
}

// ========== tensor-core GEMM (3xFP16, pre-split operands) + fused LEConv epilogue ==========
#define AH_S 20                     // u32 per A-row per stage (16 data + 4 pad): banks 20g+tq distinct
#define BH_S 68                     // u32 per B-row full-K (64 data + 4 pad): banks 4g+tq distinct
#define OFF_ALO (2 * 128 * AH_S)    // 5120 u32
#define OFF_BHI (2 * OFF_ALO)       // 10240
#define OFF_BLO (OFF_BHI + 128 * BH_S)   // 18944
#define TG_SMEM ((OFF_BLO + 128 * BH_S) * 4)  // 110592 bytes

#define MMA_F16(d, a0, a1, a2, a3, b0, b1)                                              \
    asm volatile("mma.sync.aligned.m16n8k16.row.col.f32.f16.f16.f32 "                    \
                 "{%0,%1,%2,%3},{%4,%5,%6,%7},{%8,%9},{%0,%1,%2,%3};"                    \
                 : "+f"(d[0]), "+f"(d[1]), "+f"(d[2]), "+f"(d[3])                        \
                 : "r"(a0), "r"(a1), "r"(a2), "r"(a3), "r"(b0), "r"(b1))

__global__ __launch_bounds__(256, 1) void tgemm_kernel(const __half* __restrict__ Ahi,
                                                       const __half* __restrict__ Alo,
                                                       const __half* __restrict__ Wthi,
                                                       const __half* __restrict__ Wtlo,
                                                       const float* __restrict__ bias,
                                                       const float* __restrict__ svec,
                                                       int M, int AC,
                                                       float* __restrict__ out) {
    extern __shared__ uint32_t smu[];

    const int Ncol = 3 * AC;
    const int OS   = 2 * AC;
    const int tid = threadIdx.x;
    const int lane = tid & 31;
    const int g  = lane >> 2;     // 0..7
    const int tq = lane & 3;      // 0..3
    const int warp = tid >> 5;
    const int wm = warp & 1;
    const int wn = warp >> 1;
    const int row0 = blockIdx.x * 128;
    const int col0 = blockIdx.y * 128;

    const uint32_t sb = (uint32_t)__cvta_generic_to_shared(smu);

    // ---- A stage loader: 128 rows x 16 u32 (32 halves), hi+lo, one commit group ----
    auto load_a = [&](int s, int buf) {
        #pragma unroll
        for (int p = 0; p < 2; p++) {
            int f = tid + p * 256;          // 0..511 chunks of 16B
            int row = f >> 2, c = f & 3;
            bool valid = (row0 + row) < M;
            size_t gof = (valid ? (size_t)(row0 + row) : 0) * KK + s * 32 + c * 8;
            int bytes = valid ? 16 : 0;
            uint32_t du = (uint32_t)(buf * 128 * AH_S + row * AH_S + c * 4);
            asm volatile("cp.async.ca.shared.global [%0], [%1], 16, %2;"
                         :: "r"(sb + du * 4), "l"(Ahi + gof), "r"(bytes));
            asm volatile("cp.async.ca.shared.global [%0], [%1], 16, %2;"
                         :: "r"(sb + (OFF_ALO + du) * 4), "l"(Alo + gof), "r"(bytes));
        }
        asm volatile("cp.async.commit_group;");
    };

    // ---- B loader: full-K, 128 n-rows x 64 u32, hi+lo, one commit group ----
    auto load_b = [&]() {
        #pragma unroll
        for (int p = 0; p < 8; p++) {
            int f = tid + p * 256;          // 0..2047 chunks of 16B
            int n = f >> 4, c = f & 15;
            bool valid = (col0 + n) < Ncol;
            size_t gof = (valid ? (size_t)(col0 + n) : 0) * KK + c * 8;
            int bytes = valid ? 16 : 0;
            uint32_t du = (uint32_t)(n * BH_S + c * 4);
            asm volatile("cp.async.ca.shared.global [%0], [%1], 16, %2;"
                         :: "r"(sb + (OFF_BHI + du) * 4), "l"(Wthi + gof), "r"(bytes));
            asm volatile("cp.async.ca.shared.global [%0], [%1], 16, %2;"
                         :: "r"(sb + (OFF_BLO + du) * 4), "l"(Wtlo + gof), "r"(bytes));
        }
        asm volatile("cp.async.commit_group;");
    };

    // ---- prologue: commit order A0, B, A1; wait leaves only A1 pending ----
    load_a(0, 0);
    load_b();
    load_a(1, 1);
    asm volatile("cp.async.wait_group 1;");
    __syncthreads();

    float acc[4][4][4];
    #pragma unroll
    for (int i = 0; i < 4; i++)
        #pragma unroll
        for (int j = 0; j < 4; j++)
            #pragma unroll
            for (int q = 0; q < 4; q++) acc[i][j][q] = 0.f;

    // ---- main loop: 4 stages of BK=32 halves-of-k (2 k16 steps each) ----
    #pragma unroll
    for (int t = 0; t < 4; t++) {
        const uint32_t* ah = smu + (t & 1) * (128 * AH_S);
        const uint32_t* al = ah + OFF_ALO;

        #pragma unroll
        for (int kk = 0; kk < 2; kk++) {
            uint32_t ahi[4][4], alo[4][4];
            #pragma unroll
            for (int i = 0; i < 4; i++) {
                int r0 = wm * 64 + i * 16 + g;
                int b0i = r0 * AH_S + kk * 8 + tq;
                int b1i = (r0 + 8) * AH_S + kk * 8 + tq;
                ahi[i][0] = ah[b0i];     ahi[i][1] = ah[b1i];
                ahi[i][2] = ah[b0i + 4]; ahi[i][3] = ah[b1i + 4];
                alo[i][0] = al[b0i];     alo[i][1] = al[b1i];
                alo[i][2] = al[b0i + 4]; alo[i][3] = al[b1i + 4];
            }
            uint32_t bhi[4][2], blo[4][2];
            int k16 = t * 2 + kk;
            #pragma unroll
            for (int j = 0; j < 4; j++) {
                int nn = wn * 32 + j * 8 + g;
                int bi = nn * BH_S + k16 * 8 + tq;
                bhi[j][0] = smu[OFF_BHI + bi]; bhi[j][1] = smu[OFF_BHI + bi + 4];
                blo[j][0] = smu[OFF_BLO + bi]; blo[j][1] = smu[OFF_BLO + bi + 4];
            }
            #pragma unroll
            for (int i = 0; i < 4; i++)
                #pragma unroll
                for (int j = 0; j < 4; j++) {
                    MMA_F16(acc[i][j], ahi[i][0], ahi[i][1], ahi[i][2], ahi[i][3], bhi[j][0], bhi[j][1]);
                    MMA_F16(acc[i][j], ahi[i][0], ahi[i][1], ahi[i][2], ahi[i][3], blo[j][0], blo[j][1]);
                    MMA_F16(acc[i][j], alo[i][0], alo[i][1], alo[i][2], alo[i][3], bhi[j][0], bhi[j][1]);
                }
        }

        if (t < 3) {
            __syncthreads();
            if (t + 2 < 4) load_a(t + 2, t & 1);
            asm volatile("cp.async.wait_group %0;" :: "n"(1));
            if (t == 2) asm volatile("cp.async.wait_group 0;");
            __syncthreads();
        }
    }

    // ---- fused epilogue: a-part bias add; (b,c) pair -> d = (c + b3) - s*b ----
    #pragma unroll
    for (int i = 0; i < 4; i++) {
        int gm0 = row0 + wm * 64 + i * 16 + g;
        int gm1 = gm0 + 8;
        float s0 = (gm0 < M) ? svec[gm0] : 0.f;
        float s1 = (gm1 < M) ? svec[gm1] : 0.f;
        #pragma unroll
        for (int j = 0; j < 4; j++) {
            int gn = col0 + wn * 32 + j * 8 + 2 * tq;
            if (gn >= Ncol) continue;
            if (gn < AC) {
                float2 bb = *reinterpret_cast<const float2*>(bias + gn);
                if (gm0 < M) {
                    float2 v0 = make_float2(acc[i][j][0] + bb.x, acc[i][j][1] + bb.y);
                    *reinterpret_cast<float2*>(out + (size_t)gm0 * OS + gn) = v0;
                }
                if (gm1 < M) {
                    float2 v1 = make_float2(acc[i][j][2] + bb.x, acc[i][j][3] + bb.y);
                    *reinterpret_cast<float2*>(out + (size_t)gm1 * OS + gn) = v1;
                }
            } else {
                int u = (gn - AC) >> 1;
                float b3v = bias[gn + 1];
                if (gm0 < M)
                    out[(size_t)gm0 * OS + AC + u] = (acc[i][j][1] + b3v) - s0 * acc[i][j][0];
                if (gm1 < M)
                    out[(size_t)gm1 * OS + AC + u] = (acc[i][j][3] + b3v) - s1 * acc[i][j][2];
            }
        }
    }
}

// ---------------- SpMM + epilogue, F=128: writes next layer's split fp16 activations ----------------
__global__ __launch_bounds__(256) void spmm128_kernel(const float* __restrict__ ad,
                                                      __half* __restrict__ hhi,
                                                      __half* __restrict__ hlo) {
    const int F = 128;
    const int stride = 2 * F;
    int w = blockIdx.x * 8 + (threadIdx.x >> 5);
    if (w >= NN) return;
    int lane = threadIdx.x & 31;
    int fbase = lane * 4;

    float4 acc = make_float4(0.f, 0.f, 0.f, 0.f);
    int beg = g_rowptr[w], end = g_rowptr[w + 1];
    int e = beg;
    for (; e + 3 < end; e += 4) {
        int   s0 = g_src[e],   s1 = g_src[e+1], s2 = g_src[e+2], s3 = g_src[e+3];
        float w0 = g_ew[e],    w1 = g_ew[e+1],  w2 = g_ew[e+2],  w3 = g_ew[e+3];
        float4 a0 = *reinterpret_cast<const float4*>(ad + (size_t)s0 * stride + fbase);
        float4 a1 = *reinterpret_cast<const float4*>(ad + (size_t)s1 * stride + fbase);
        float4 a2 = *reinterpret_cast<const float4*>(ad + (size_t)s2 * stride + fbase);
        float4 a3 = *reinterpret_cast<const float4*>(ad + (size_t)s3 * stride + fbase);
        acc.x += w0 * a0.x + w1 * a1.x + w2 * a2.x + w3 * a3.x;
        acc.y += w0 * a0.y + w1 * a1.y + w2 * a2.y + w3 * a3.y;
        acc.z += w0 * a0.z + w1 * a1.z + w2 * a2.z + w3 * a3.z;
        acc.w += w0 * a0.w + w1 * a1.w + w2 * a2.w + w3 * a3.w;
    }
    for (; e < end; e++) {
        int   s0 = g_src[e];
        float w0 = g_ew[e];
        float4 a0 = *reinterpret_cast<const float4*>(ad + (size_t)s0 * stride + fbase);
        acc.x += w0 * a0.x; acc.y += w0 * a0.y; acc.z += w0 * a0.z; acc.w += w0 * a0.w;
    }
    float4 dv = *reinterpret_cast<const float4*>(ad + (size_t)w * stride + F + fbase);
    float v[4];
    v[0] = acc.x + dv.x;
    v[1] = acc.y + dv.y;
    v[2] = acc.z + dv.z;
    v[3] = acc.w + dv.w;
    #pragma unroll
    for (int i = 0; i < 4; i++)
        v[i] = v[i] > 0.f ? v[i] : 0.1f * v[i];

    __half2 h01 = __float22half2_rn(make_float2(v[0], v[1]));
    __half2 h23 = __float22half2_rn(make_float2(v[2], v[3]));
    float2 f01 = __half22float2(h01);
    float2 f23 = __half22float2(h23);
    __half2 l01 = __float22half2_rn(make_float2(v[0] - f01.x, v[1] - f01.y));
    __half2 l23 = __float22half2_rn(make_float2(v[2] - f23.x, v[3] - f23.y));
    uint2 uh = make_uint2(*reinterpret_cast<uint32_t*>(&h01), *reinterpret_cast<uint32_t*>(&h23));
    uint2 ul = make_uint2(*reinterpret_cast<uint32_t*>(&l01), *reinterpret_cast<uint32_t*>(&l23));
    *reinterpret_cast<uint2*>(hhi + (size_t)w * F + fbase) = uh;
    *reinterpret_cast<uint2*>(hlo + (size_t)w * F + fbase) = ul;
}

// ---------------- SpMM + epilogue, F=64 (final layer, fp32 out, lrelu+sigmoid) ----------------
__global__ __launch_bounds__(256) void spmm64_kernel(const float* __restrict__ ad,
                                                     float* __restrict__ out) {
    const int F = 64;
    const int stride = 2 * F;
    int w = blockIdx.x * 8 + (threadIdx.x >> 5);
    if (w >= NN) return;
    int lane = threadIdx.x & 31;
    int fbase = lane * 2;

    float2 acc = make_float2(0.f, 0.f);
    int beg = g_rowptr[w], end = g_rowptr[w + 1];
    int e = beg;
    for (; e + 3 < end; e += 4) {
        int   s0 = g_src[e],   s1 = g_src[e+1], s2 = g_src[e+2], s3 = g_src[e+3];
        float w0 = g_ew[e],    w1 = g_ew[e+1],  w2 = g_ew[e+2],  w3 = g_ew[e+3];
        float2 a0 = *reinterpret_cast<const float2*>(ad + (size_t)s0 * stride + fbase);
        float2 a1 = *reinterpret_cast<const float2*>(ad + (size_t)s1 * stride + fbase);
        float2 a2 = *reinterpret_cast<const float2*>(ad + (size_t)s2 * stride + fbase);
        float2 a3 = *reinterpret_cast<const float2*>(ad + (size_t)s3 * stride + fbase);
        acc.x += w0 * a0.x + w1 * a1.x + w2 * a2.x + w3 * a3.x;
        acc.y += w0 * a0.y + w1 * a1.y + w2 * a2.y + w3 * a3.y;
    }
    for (; e < end; e++) {
        int   s0 = g_src[e];
        float w0 = g_ew[e];
        float2 a0 = *reinterpret_cast<const float2*>(ad + (size_t)s0 * stride + fbase);
        acc.x += w0 * a0.x; acc.y += w0 * a0.y;
    }
    float2 dv = *reinterpret_cast<const float2*>(ad + (size_t)w * stride + F + fbase);
    float v[2];
    v[0] = acc.x + dv.x;
    v[1] = acc.y + dv.y;
    #pragma unroll
    for (int i = 0; i < 2; i++) {
        float t = v[i] > 0.f ? v[i] : 0.1f * v[i];
        v[i] = 1.f / (1.f + expf(-t));
    }
    *reinterpret_cast<float2*>(out + (size_t)w * F + fbase) = make_float2(v[0], v[1]);
}

// ---------------- host launch ----------------
extern "C" void kernel_launch(void* const* d_in, const int* in_sizes, int n_in,
                              void* d_out, int out_size) {
    const float* x  = (const float*)d_in[0];
    const void*  ei = d_in[1];
    const float* ea = (const float*)d_in[2];
    const float* W1_in  = (const float*)d_in[4];
    const float* b1_in  = (const float*)d_in[5];
    const float* W2_in  = (const float*)d_in[6];
    const float* W3_in  = (const float*)d_in[7];
    const float* b3_in  = (const float*)d_in[8];
    const float* W1_mid = (const float*)d_in[9];
    const float* b1_mid = (const float*)d_in[10];
    const float* W2_mid = (const float*)d_in[11];
    const float* W3_mid = (const float*)d_in[12];
    const float* b3_mid = (const float*)d_in[13];
    const float* W1_out = (const float*)d_in[14];
    const float* b1_out = (const float*)d_in[15];
    const float* W2_out = (const float*)d_in[16];
    const float* W3_out = (const float*)d_in[17];
    const float* b3_out = (const float*)d_in[18];

    float* out = (float*)d_out;

    float *d_abc, *d_b0, *d_b1, *d_b2, *d_s;
    __half *d_Ahi, *d_Alo, *d_Wh0, *d_Wl0, *d_Wh1, *d_Wl1, *d_Wh2, *d_Wl2;
    cudaGetSymbolAddress((void**)&d_abc, g_abc);
    cudaGetSymbolAddress((void**)&d_Ahi, g_Ahi);
    cudaGetSymbolAddress((void**)&d_Alo, g_Alo);
    cudaGetSymbolAddress((void**)&d_Wh0, g_Wthi0);
    cudaGetSymbolAddress((void**)&d_Wl0, g_Wtlo0);
    cudaGetSymbolAddress((void**)&d_Wh1, g_Wthi1);
    cudaGetSymbolAddress((void**)&d_Wl1, g_Wtlo1);
    cudaGetSymbolAddress((void**)&d_Wh2, g_Wthi2);
    cudaGetSymbolAddress((void**)&d_Wl2, g_Wtlo2);
    cudaGetSymbolAddress((void**)&d_b0,  g_bcat0);
    cudaGetSymbolAddress((void**)&d_b1,  g_bcat1);
    cudaGetSymbolAddress((void**)&d_b2,  g_bcat2);
    cudaGetSymbolAddress((void**)&d_s,   g_s);

    cudaFuncSetAttribute(tgemm_kernel, cudaFuncAttributeMaxDynamicSharedMemorySize, TG_SMEM);

    // --- pack weights (pre-split, transposed) + split x ---
    pack_w_kernel<<<(F_IN * WID + 255) / 256, 256>>>(W1_in,  b1_in,  W2_in,  W3_in,  b3_in,  F_IN, WID,   d_Wh0, d_Wl0, d_b0);
    pack_w_kernel<<<(WID * WID + 255) / 256, 256>>>(W1_mid, b1_mid, W2_mid, W3_mid, b3_mid, WID,  WID,   d_Wh1, d_Wl1, d_b1);
    pack_w_kernel<<<(WID * F_OUT + 255) / 256, 256>>>(W1_out, b1_out, W2_out, W3_out, b3_out, WID, F_OUT, d_Wh2, d_Wl2, d_b2);
    convert_x_kernel<<<(NN * KK / 4 + 255) / 256, 256>>>((const float4*)x, NN * KK / 4);

    // --- preprocessing: zero+detect, s[i], CSR ---
    zero_kernel<<<(NN + 255) / 256, 256>>>((const int*)ei);
    hist_kernel<<<(EE + 255) / 256, 256>>>(ei, ea);
    scan1_kernel<<<SCAN_NB, SCAN_B>>>();
    scan2_kernel<<<1, 32>>>();
    scan3_kernel<<<SCAN_NB, SCAN_B>>>();
    scatter_kernel<<<(EE + 255) / 256, 256>>>(ei, ea);

    const int spmm_blocks = (NN + 7) / 8;
    const int grid_m = (NN + 127) / 128;

    // --- layer 0 (in) ---
    {
        dim3 grid(grid_m, (3 * WID + 127) / 128);
        tgemm_kernel<<<grid, 256, TG_SMEM>>>(d_Ahi, d_Alo, d_Wh0, d_Wl0, d_b0, d_s, NN, WID, d_abc);
        spmm128_kernel<<<spmm_blocks, 256>>>(d_abc, d_Ahi, d_Alo);
    }

    // --- layers 1,2 (mid) ---
    for (int l = 0; l < 2; l++) {
        dim3 grid(grid_m, (3 * WID + 127) / 128);
        tgemm_kernel<<<grid, 256, TG_SMEM>>>(d_Ahi, d_Alo, d_Wh1, d_Wl1, d_b1, d_s, NN, WID, d_abc);
        spmm128_kernel<<<spmm_blocks, 256>>>(d_abc, d_Ahi, d_Alo);
    }

    // --- layer 3 (out): lrelu+sigmoid, fp32 out ---
    {
        dim3 grid(grid_m, (3 * F_OUT + 127) / 128);
        tgemm_kernel<<<grid, 256, TG_SMEM>>>(d_Ahi, d_Alo, d_Wh2, d_Wl2, d_b2, d_s, NN, F_OUT, d_abc);
        spmm64_kernel<<<spmm_blocks, 256>>>(d_abc, out);
    }
}